// round 11
// baseline (speedup 1.0000x reference)
#include <cuda_runtime.h>

#define NPTS 1024

// ---------------- packed f32x2 helpers (Blackwell) ----------------
static __device__ __forceinline__ unsigned long long pack2(float lo, float hi) {
    unsigned long long r;
    asm("mov.b64 %0, {%1,%2};" : "=l"(r) : "f"(lo), "f"(hi));
    return r;
}
static __device__ __forceinline__ float2 unpack2(unsigned long long v) {
    float2 r;
    asm("mov.b64 {%0,%1}, %2;" : "=f"(r.x), "=f"(r.y) : "l"(v));
    return r;
}
static __device__ __forceinline__ void fma2(unsigned long long& d,
                                            unsigned long long a,
                                            unsigned long long b) {
    asm("fma.rn.f32x2 %0, %1, %2, %0;" : "+l"(d) : "l"(a), "l"(b));
}

// ============================================================================
// Fused kernel: 256 blocks x 256 threads; block b owns rows 4b..4b+3.
// Phase P (pool): LSU-balanced conv2.
//   Thread = (kq = lane bits 0-1: 16-k quarter, chq: 4 channels {chq+32c},
//   nnh: 4 of 8 nbrs). Per 8-nbr set: 16 LDS.128 feed 128 fma2 (ratio 8 --
//   R10 measured LSU-bound at ratio 4). k-quarters combined via
//   shfl_xor(1)+shfl_xor(2). h1 slot = 80 floats, quarter at +20*kq so the
//   warp's 4 addresses hit disjoint bank groups for all q.
// Phase T (trunk): feat[132]->64->128->64->4 -> (a_x,a_y), f32x2 GEMV.
// ============================================================================

// ---- shared memory layout (bytes) ----
// Phase P: s4 @0 [16384] | nbr @16384 [4][256]*4 | h1 @20480 [32][80]*4=10240
//          w1s @30720 [320]*4 | b1s @32000 [64]*4 | part @32256 [128]*4
// Phase T: wP @0 u64[66*65]=34320 | w4 @34320 | bb1 @35344 | bb2 @35600 |
//          bb3 @36112 | b4s @36368
// Persist: cnt @36384 int[8] | feat @36416 [4][132]*4 -> end 38528
#define SM_TOTAL 38528

__global__ __launch_bounds__(256, 2) void fused_kernel(
    const float* __restrict__ s, const float* __restrict__ g,
    const float* __restrict__ w1g, const float* __restrict__ b1g,
    const float* __restrict__ w2g, const float* __restrict__ b2g,
    const float* __restrict__ fc1w, const float* __restrict__ fc1b,
    const float* __restrict__ fc2w, const float* __restrict__ fc2b,
    const float* __restrict__ fc3w, const float* __restrict__ fc3b,
    const float* __restrict__ fc4w, const float* __restrict__ fc4b,
    float* __restrict__ out)
{
    __shared__ __align__(16) char smem_raw[SM_TOTAL];

    const int tid = threadIdx.x;

    // ======================= PHASE P: pool =======================
    float4* s4   = reinterpret_cast<float4*>(smem_raw);
    int (*nbr)[256] = reinterpret_cast<int(*)[256]>(smem_raw + 16384);
    float* h1    = reinterpret_cast<float*>(smem_raw + 20480);   // [32][80]
    float* w1s   = reinterpret_cast<float*>(smem_raw + 30720);
    float* b1s   = reinterpret_cast<float*>(smem_raw + 32000);
    float* part  = reinterpret_cast<float*>(smem_raw + 32256);   // [128]
    int*   cnt   = reinterpret_cast<int*>(smem_raw + 36384);
    int*   cntp  = cnt + 4;
    float (*feat)[132] = reinterpret_cast<float(*)[132]>(smem_raw + 36416);

    const int kq  = tid & 3;            // k-quarter (lane bits 0-1)
    const int chq = (tid >> 2) & 31;    // channel quad: ch {chq + 32c}
    const int nnh = tid >> 7;           // neighbor half (4 of each 8)

    // conv2 weights: 4 ch x 16 k (this quarter): 16 LDG.128 -> 32 packs (64 regs)
    unsigned long long w2p[4][8];
    float b2r[4];
#pragma unroll
    for (int c = 0; c < 4; c++) {
        int ch = chq + 32 * c;
        const float4* wr = reinterpret_cast<const float4*>(w2g + ch * 64 + kq * 16);
        float4 wv[4];
#pragma unroll
        for (int q = 0; q < 4; q++) wv[q] = wr[q];
#pragma unroll
        for (int q = 0; q < 4; q++) {
            w2p[c][2 * q]     = pack2(wv[q].x, wv[q].y);
            w2p[c][2 * q + 1] = pack2(wv[q].z, wv[q].w);
        }
        b2r[c] = b2g[ch];
    }

    // stage s (4 batched LDG.128 each), w1, b1; reset counters
#pragma unroll
    for (int j = 0; j < 4; j++)
        s4[tid + 256 * j] = reinterpret_cast<const float4*>(s)[tid + 256 * j];
    for (int idx = tid; idx < 320; idx += 256) w1s[idx] = w1g[idx];
    if (tid < 64) b1s[tid] = b1g[tid];
    if (tid < 4)  cnt[tid] = 0;
    __syncthreads();

    const int   c1  = tid & 63;   // conv1 channel this thread computes
    const int   slb = tid >> 6;   // conv1 slot base: slots {slb + 4t}
    const float w1r0 = w1s[c1 * 5 + 0], w1r1 = w1s[c1 * 5 + 1],
                w1r2 = w1s[c1 * 5 + 2], w1r3 = w1s[c1 * 5 + 3],
                w1r4 = w1s[c1 * 5 + 4], b1r = b1s[c1];
    const int   h1wr = (c1 >> 4) * 20 + (c1 & 15);   // conv1 write offset in slot

    const int i0 = blockIdx.x * 4;
    float4 si[4];
#pragma unroll
    for (int rr = 0; rr < 4; rr++) si[rr] = s4[i0 + rr];

    // ---- one scan pass serves all 4 rows ----
    for (int j = tid; j < NPTS; j += 256) {
        float4 sj = s4[j];
#pragma unroll
        for (int rr = 0; rr < 4; rr++) {
            float dx = si[rr].x - sj.x, dy = si[rr].y - sj.y;
            if (dx * dx + dy * dy < 0.25f) {
                int pq = atomicAdd(&cnt[rr], 1);
                nbr[rr][pq] = j;
            }
        }
    }
    __syncthreads();
    if (tid < 4) {
        int c = cnt[tid], cp = (c + 7) & ~7;
        for (int t = c; t < cp; t++) nbr[tid][t] = i0 + tid;  // self-pad (idempotent)
        cntp[tid] = cp;
    }
    __syncthreads();

    // ---- pool: 32-neighbor chunks; conv2 sweeps barrier-free ----
#pragma unroll 1
    for (int rr = 0; rr < 4; rr++) {
        const float4 sir = si[rr];
        const int    i   = i0 + rr;
        const int    cp  = cntp[rr];
        const int*   nb  = nbr[rr];
        float p0 = 0.0f, p1 = 0.0f, p2 = 0.0f, p3 = 0.0f;  // max vs 0 = mask/relu

        for (int chunk = 0; chunk < cp; chunk += 32) {
            const int clen = min(32, cp - chunk);   // multiple of 8

            // conv1: fill h1 for clen slots (8 slots/thread, warp-uniform guard)
#pragma unroll
            for (int t = 0; t < 8; t++) {
                int sl = slb + 4 * t;
                if (sl < clen) {
                    int j = nb[chunk + sl];
                    float4 sj = s4[j];
                    float dx = sir.x - sj.x, dy = sir.y - sj.y;
                    float dz = sir.z - sj.z, dw = sir.w - sj.w;
                    float ind = (j == i) ? 1.0f : 0.0f;
                    float v = b1r;
                    v = fmaf(dx, w1r0, v);
                    v = fmaf(dy, w1r1, v);
                    v = fmaf(dz, w1r2, v);
                    v = fmaf(dw, w1r3, v);
                    v = fmaf(ind, w1r4, v);
                    h1[sl * 80 + h1wr] = fmaxf(v, 0.0f);
                }
            }
            __syncthreads();   // h1 chunk ready

            // conv2 sweep: 8-nbr sets, no barriers inside the chunk
            for (int n = 0; n < clen; n += 8) {
                const float* hb = h1 + (n + nnh * 4) * 80 + kq * 20;
                unsigned long long acc[4][4];   // [nbr][ch]
#pragma unroll
                for (int t = 0; t < 4; t++)
#pragma unroll
                    for (int c = 0; c < 4; c++) acc[t][c] = 0ull;

#pragma unroll
                for (int t = 0; t < 4; t++) {
#pragma unroll
                    for (int q = 0; q < 4; q++) {
                        // warp: 4 distinct addrs (kq), disjoint bank groups
                        ulonglong2 hp = *reinterpret_cast<const ulonglong2*>(
                            hb + t * 80 + q * 4);
                        fma2(acc[t][0], hp.x, w2p[0][2 * q]);
                        fma2(acc[t][1], hp.x, w2p[1][2 * q]);
                        fma2(acc[t][2], hp.x, w2p[2][2 * q]);
                        fma2(acc[t][3], hp.x, w2p[3][2 * q]);
                        fma2(acc[t][0], hp.y, w2p[0][2 * q + 1]);
                        fma2(acc[t][1], hp.y, w2p[1][2 * q + 1]);
                        fma2(acc[t][2], hp.y, w2p[2][2 * q + 1]);
                        fma2(acc[t][3], hp.y, w2p[3][2 * q + 1]);
                    }
                }
                // combine k-quarters: shfl_xor over lane bits 0-1, then max
#pragma unroll
                for (int t = 0; t < 4; t++) {
                    float2 f0 = unpack2(acc[t][0]);
                    float2 f1 = unpack2(acc[t][1]);
                    float2 f2 = unpack2(acc[t][2]);
                    float2 f3 = unpack2(acc[t][3]);
                    float s0 = f0.x + f0.y, s1 = f1.x + f1.y;
                    float s2 = f2.x + f2.y, s3 = f3.x + f3.y;
                    s0 += __shfl_xor_sync(0xffffffffu, s0, 1);
                    s1 += __shfl_xor_sync(0xffffffffu, s1, 1);
                    s2 += __shfl_xor_sync(0xffffffffu, s2, 1);
                    s3 += __shfl_xor_sync(0xffffffffu, s3, 1);
                    s0 += __shfl_xor_sync(0xffffffffu, s0, 2);
                    s1 += __shfl_xor_sync(0xffffffffu, s1, 2);
                    s2 += __shfl_xor_sync(0xffffffffu, s2, 2);
                    s3 += __shfl_xor_sync(0xffffffffu, s3, 2);
                    p0 = fmaxf(p0, s0 + b2r[0]);
                    p1 = fmaxf(p1, s1 + b2r[1]);
                    p2 = fmaxf(p2, s2 + b2r[2]);
                    p3 = fmaxf(p3, s3 + b2r[3]);
                }
            }
            __syncthreads();   // all h1 reads done before refill
        }

        // combine the two nnh halves for this row (part reused per row)
        if (nnh == 1 && kq == 0) {
            part[chq]      = p0;
            part[chq + 32] = p1;
            part[chq + 64] = p2;
            part[chq + 96] = p3;
        }
        __syncthreads();
        if (nnh == 0 && kq == 0) {
            feat[rr][chq]      = fmaxf(p0, part[chq]);
            feat[rr][chq + 32] = fmaxf(p1, part[chq + 32]);
            feat[rr][chq + 64] = fmaxf(p2, part[chq + 64]);
            feat[rr][chq + 96] = fmaxf(p3, part[chq + 96]);
        }
        __syncthreads();
    }

    // ======================= PHASE T: trunk =======================
    unsigned long long* wP = reinterpret_cast<unsigned long long*>(smem_raw);
    float* w4  = reinterpret_cast<float*>(smem_raw + 34320);
    float* bb1 = reinterpret_cast<float*>(smem_raw + 35344);
    float* bb2 = reinterpret_cast<float*>(smem_raw + 35600);
    float* bb3 = reinterpret_cast<float*>(smem_raw + 36112);
    float* b4s = reinterpret_cast<float*>(smem_raw + 36368);
    float (*act)[132] = feat;   // same storage (outside trunk weight area)

    const int lane   = tid & 31;
    const int w      = tid >> 5;
    const bool active = (w < 4);
    const int r      = i0 + (active ? w : 0);

    float4 sv = make_float4(0.f, 0.f, 0.f, 0.f);
    float2 gv = make_float2(0.f, 0.f);
    if (active) {
        sv = reinterpret_cast<const float4*>(s)[r];
        gv = reinterpret_cast<const float2*>(g)[r];
        if (lane == 0) {
            act[w][128] = sv.x - gv.x;
            act[w][129] = sv.y - gv.y;
            act[w][130] = sv.z;
            act[w][131] = sv.w;
        }
    }

    // fc1 staging loads: 2112 float4, register-buffered
    const float4* f1w4 = reinterpret_cast<const float4*>(fc1w);
    float4 v1[8];
#pragma unroll
    for (int rr = 0; rr < 8; rr++) v1[rr] = f1w4[tid + 256 * rr];
    float4 v1x;
    if (tid < 64) v1x = f1w4[2048 + tid];

    // biases + fc4
    if (tid < 64)  bb1[tid] = fc1b[tid];
    if (tid < 128) bb2[tid] = fc2b[tid];
    if (tid >= 128 && tid < 192) bb3[tid - 128] = fc3b[tid - 128];
    if (tid < 4)   b4s[tid] = fc4b[tid];
    if (tid < 64) {                       // fc4: 64 float4s
        float4 v = reinterpret_cast<const float4*>(fc4w)[tid];
        int o = tid >> 4;
        int k = (tid << 2) & 63;
        w4[(k + 0) * 4 + o] = v.x; w4[(k + 1) * 4 + o] = v.y;
        w4[(k + 2) * 4 + o] = v.z; w4[(k + 3) * 4 + o] = v.w;
    }

    // STS fc1 as k-pair u64: wP[k2*65 + o]
#pragma unroll
    for (int rr = 0; rr < 8; rr++) {
        int e = (tid + 256 * rr) << 2;
        int o = e / 132;                  // 132 % 4 == 0: no row straddle
        int k = e - o * 132;
        int k2 = k >> 1;
        wP[(k2 + 0) * 65 + o] = pack2(v1[rr].x, v1[rr].y);
        wP[(k2 + 1) * 65 + o] = pack2(v1[rr].z, v1[rr].w);
    }
    if (tid < 64) {
        int e = (2048 + tid) << 2;
        int o = e / 132;
        int k = e - o * 132;
        int k2 = k >> 1;
        wP[(k2 + 0) * 65 + o] = pack2(v1x.x, v1x.y);
        wP[(k2 + 1) * 65 + o] = pack2(v1x.z, v1x.w);
    }
    __syncthreads();

    // prefetch fc2 before L1 compute
    const float4* f2w4 = reinterpret_cast<const float4*>(fc2w);
    float4 v2[8];
#pragma unroll
    for (int rr = 0; rr < 8; rr++) v2[rr] = f2w4[tid + 256 * rr];

    // L1: 132 -> 64
    {
        float a0 = 0.f, a1 = 0.f;
        if (active) {
            const unsigned long long* actp =
                reinterpret_cast<const unsigned long long*>(act[w]);
            unsigned long long a0p = 0ull, a1p = 0ull;
#pragma unroll 6
            for (int k2 = 0; k2 < 66; k2++) {
                unsigned long long ap = actp[k2];
                fma2(a0p, ap, wP[k2 * 65 + lane]);
                fma2(a1p, ap, wP[k2 * 65 + lane + 32]);
            }
            float2 f0 = unpack2(a0p), f1 = unpack2(a1p);
            a0 = fmaxf(f0.x + f0.y + bb1[lane], 0.0f);
            a1 = fmaxf(f1.x + f1.y + bb1[lane + 32], 0.0f);
        }
        __syncthreads();
        if (active) { act[w][lane] = a0; act[w][lane + 32] = a1; }
    }

    // STS fc2: [128][64] -> wP[k2*129 + o]
#pragma unroll
    for (int rr = 0; rr < 8; rr++) {
        int e = (tid + 256 * rr) << 2;
        int o = e >> 6;
        int k = e & 63;
        int k2 = k >> 1;
        wP[(k2 + 0) * 129 + o] = pack2(v2[rr].x, v2[rr].y);
        wP[(k2 + 1) * 129 + o] = pack2(v2[rr].z, v2[rr].w);
    }
    __syncthreads();

    // prefetch fc3 before L2 compute
    const float4* f3w4 = reinterpret_cast<const float4*>(fc3w);
    float4 v3[8];
#pragma unroll
    for (int rr = 0; rr < 8; rr++) v3[rr] = f3w4[tid + 256 * rr];

    // L2: 64 -> 128
    {
        float o0 = 0.f, o1 = 0.f, o2 = 0.f, o3 = 0.f;
        if (active) {
            const unsigned long long* actp =
                reinterpret_cast<const unsigned long long*>(act[w]);
            unsigned long long ac[4] = {0ull, 0ull, 0ull, 0ull};
#pragma unroll 4
            for (int k2 = 0; k2 < 32; k2++) {
                unsigned long long ap = actp[k2];
                fma2(ac[0], ap, wP[k2 * 129 + lane]);
                fma2(ac[1], ap, wP[k2 * 129 + lane + 32]);
                fma2(ac[2], ap, wP[k2 * 129 + lane + 64]);
                fma2(ac[3], ap, wP[k2 * 129 + lane + 96]);
            }
            { float2 f = unpack2(ac[0]); o0 = fmaxf(f.x + f.y + bb2[lane],      0.0f); }
            { float2 f = unpack2(ac[1]); o1 = fmaxf(f.x + f.y + bb2[lane + 32], 0.0f); }
            { float2 f = unpack2(ac[2]); o2 = fmaxf(f.x + f.y + bb2[lane + 64], 0.0f); }
            { float2 f = unpack2(ac[3]); o3 = fmaxf(f.x + f.y + bb2[lane + 96], 0.0f); }
        }
        __syncthreads();
        if (active) {
            act[w][lane] = o0; act[w][lane + 32] = o1;
            act[w][lane + 64] = o2; act[w][lane + 96] = o3;
        }
    }

    // STS fc3: [64][128] -> wP[k2*65 + o]
#pragma unroll
    for (int rr = 0; rr < 8; rr++) {
        int e = (tid + 256 * rr) << 2;
        int o = e >> 7;
        int k = e & 127;
        int k2 = k >> 1;
        wP[(k2 + 0) * 65 + o] = pack2(v3[rr].x, v3[rr].y);
        wP[(k2 + 1) * 65 + o] = pack2(v3[rr].z, v3[rr].w);
    }
    __syncthreads();

    if (active) {
        // L3: 128 -> 64 (warp-private from here on)
        const unsigned long long* actp =
            reinterpret_cast<const unsigned long long*>(act[w]);
        unsigned long long a0p = 0ull, a1p = 0ull;
#pragma unroll 8
        for (int k2 = 0; k2 < 64; k2++) {
            unsigned long long ap = actp[k2];
            fma2(a0p, ap, wP[k2 * 65 + lane]);
            fma2(a1p, ap, wP[k2 * 65 + lane + 32]);
        }
        float2 f0 = unpack2(a0p), f1 = unpack2(a1p);
        float a0 = fmaxf(f0.x + f0.y + bb3[lane], 0.0f);
        float a1 = fmaxf(f1.x + f1.y + bb3[lane + 32], 0.0f);
        __syncwarp();
        act[w][lane] = a0; act[w][lane + 32] = a1;
        __syncwarp();

        // L4: 64 -> 4, sigmoid, gains
        int ol = lane & 3;
        float acc = b4s[ol];
#pragma unroll 4
        for (int k = 0; k < 64; k++)
            acc = fmaf(act[w][k], w4[k * 4 + ol], acc);
        float kv = 2.0f / (1.0f + expf(-acc)) - 1.0f;

        float k1 = __shfl_sync(0xffffffffu, kv, 0);
        float k2 = __shfl_sync(0xffffffffu, kv, 1);
        float k3 = __shfl_sync(0xffffffffu, kv, 2);
        float k4 = __shfl_sync(0xffffffffu, kv, 3);

        if (lane == 0) {
            float sg0 = sv.x - gv.x;
            float sg1 = sv.y - gv.y;
            out[r * 2 + 0] = -(k1 * sg0 + k2 * sv.z);
            out[r * 2 + 1] = -(k3 * sg1 + k4 * sv.w);
        }
    }
}

// ============================================================================
extern "C" void kernel_launch(void* const* d_in, const int* in_sizes, int n_in,
                              void* d_out, int out_size)
{
    const float* s    = (const float*)d_in[0];
    const float* g    = (const float*)d_in[1];
    const float* c1w  = (const float*)d_in[2];
    const float* c1b  = (const float*)d_in[3];
    const float* c2w  = (const float*)d_in[4];
    const float* c2b  = (const float*)d_in[5];
    const float* f1w  = (const float*)d_in[6];
    const float* f1b  = (const float*)d_in[7];
    const float* f2w  = (const float*)d_in[8];
    const float* f2b  = (const float*)d_in[9];
    const float* f3w  = (const float*)d_in[10];
    const float* f3b  = (const float*)d_in[11];
    const float* f4w  = (const float*)d_in[12];
    const float* f4b  = (const float*)d_in[13];
    float* out = (float*)d_out;

    fused_kernel<<<NPTS / 4, 256>>>(s, g, c1w, c1b, c2w, c2b,
                                    f1w, f1b, f2w, f2b, f3w, f3b,
                                    f4w, f4b, out);
}

// round 13
// speedup vs baseline: 1.9251x; 1.9251x over previous
#include <cuda_runtime.h>
#include <cuda_bf16.h>
#include <cstdint>

#define NPTS 1024

// ---------------- packed f32x2 helpers (trunk) ----------------
static __device__ __forceinline__ unsigned long long pack2(float lo, float hi) {
    unsigned long long r;
    asm("mov.b64 %0, {%1,%2};" : "=l"(r) : "f"(lo), "f"(hi));
    return r;
}
static __device__ __forceinline__ float2 unpack2(unsigned long long v) {
    float2 r;
    asm("mov.b64 {%0,%1}, %2;" : "=f"(r.x), "=f"(r.y) : "l"(v));
    return r;
}
static __device__ __forceinline__ void fma2(unsigned long long& d,
                                            unsigned long long a,
                                            unsigned long long b) {
    asm("fma.rn.f32x2 %0, %1, %2, %0;" : "+l"(d) : "l"(a), "l"(b));
}

static __device__ __forceinline__ uint32_t smem_u32(const void* p) {
    uint32_t a;
    asm("{ .reg .u64 t; cvta.to.shared.u64 t, %1; cvt.u32.u64 %0, t; }" : "=r"(a) : "l"(p));
    return a;
}

// split float pair into bf16 hi-pair and bf16 residual(lo)-pair, packed u32
static __device__ __forceinline__ void split2(float x, float y,
                                              uint32_t& hi, uint32_t& lo) {
    __nv_bfloat16 hx = __float2bfloat16(x), hy = __float2bfloat16(y);
    __nv_bfloat16 lx = __float2bfloat16(x - __bfloat162float(hx));
    __nv_bfloat16 ly = __float2bfloat16(y - __bfloat162float(hy));
    hi = (uint32_t)__bfloat16_as_ushort(hx) | ((uint32_t)__bfloat16_as_ushort(hy) << 16);
    lo = (uint32_t)__bfloat16_as_ushort(lx) | ((uint32_t)__bfloat16_as_ushort(ly) << 16);
}

// m16n8k16 row.col bf16 MMA, f32 accum (baseline PTX, works at .target sm_103)
static __device__ __forceinline__ void mma_bf16(float& c0, float& c1, float& c2, float& c3,
                                                uint32_t a0, uint32_t a1, uint32_t a2, uint32_t a3,
                                                uint32_t b0, uint32_t b1) {
    asm volatile(
        "mma.sync.aligned.m16n8k16.row.col.f32.bf16.bf16.f32 "
        "{%0,%1,%2,%3}, {%4,%5,%6,%7}, {%8,%9}, {%0,%1,%2,%3};"
        : "+f"(c0), "+f"(c1), "+f"(c2), "+f"(c3)
        : "r"(a0), "r"(a1), "r"(a2), "r"(a3), "r"(b0), "r"(b1));
}
static __device__ __forceinline__ void ldmat4(uint32_t& r0, uint32_t& r1,
                                              uint32_t& r2, uint32_t& r3, uint32_t addr) {
    asm volatile("ldmatrix.sync.aligned.m8n8.x4.shared.b16 {%0,%1,%2,%3}, [%4];"
                 : "=r"(r0), "=r"(r1), "=r"(r2), "=r"(r3) : "r"(addr));
}

// ---- static shared layout (bytes) ----
// Pool:  s4 @0 [16384] | nbr @16384 [4096] | h1hi @20480 [64*144=9216]
//        h1lo @29696 [9216] | w1s @38912 [1280] | b1s @40192 [256]
//        b2s @40448 [512] | cnt @40960 [32]
// Trunk overlay (pool area dead): wP @0 u64[66*65]=34320 | w4 @34320 |
//        bb1 @35344 | bb2 @35600 | bb3 @36112 | b4s @36368
// Persist: feat @40992 [4][132]*4 = 2112  -> total 43104
#define H1HI_OFF 20480
#define H1LO_OFF 29696
#define SM_TOTAL 43104

extern "C" __global__ __launch_bounds__(256) void fused_kernel(
    const float* __restrict__ s, const float* __restrict__ g,
    const float* __restrict__ w1g, const float* __restrict__ b1g,
    const float* __restrict__ w2g, const float* __restrict__ b2g,
    const float* __restrict__ fc1w, const float* __restrict__ fc1b,
    const float* __restrict__ fc2w, const float* __restrict__ fc2b,
    const float* __restrict__ fc3w, const float* __restrict__ fc3b,
    const float* __restrict__ fc4w, const float* __restrict__ fc4b,
    float* __restrict__ out)
{
    __shared__ __align__(16) char smem_raw[SM_TOTAL];

    const int tid  = threadIdx.x;
    const int lane = tid & 31;
    const int wrp  = tid >> 5;
    const uint32_t smb = smem_u32(smem_raw);

    float4* s4 = reinterpret_cast<float4*>(smem_raw);
    int (*nbr)[256] = reinterpret_cast<int(*)[256]>(smem_raw + 16384);
    char* h1hi = smem_raw + H1HI_OFF;
    char* h1lo = smem_raw + H1LO_OFF;
    float* w1s = reinterpret_cast<float*>(smem_raw + 38912);
    float* b1s = reinterpret_cast<float*>(smem_raw + 40192);
    float* b2s = reinterpret_cast<float*>(smem_raw + 40448);
    int*   cnt = reinterpret_cast<int*>(smem_raw + 40960);
    int*   cntp = cnt + 4;
    float (*feat)[132] = reinterpret_cast<float(*)[132]>(smem_raw + 40992);

    // ---- stage s, w1, b1, b2; reset counters ----
#pragma unroll
    for (int j = 0; j < 4; j++)
        s4[tid + 256 * j] = reinterpret_cast<const float4*>(s)[tid + 256 * j];
    for (int idx = tid; idx < 320; idx += 256) w1s[idx] = w1g[idx];
    if (tid < 64)  b1s[tid] = b1g[tid];
    if (tid < 128) b2s[tid] = b2g[tid];
    if (tid < 4)   cnt[tid] = 0;

    // ---- B fragments (conv2 weights) in registers: warp wrp owns 16 ch ----
    // m16n8k16 col-B mapping: n = lane>>2, k = ks*16 + 2*(lane&3) (+1, +8, +9)
    uint32_t bhi[2][4][2], blo[2][4][2];
    {
        const int n = wrp * 16 + (lane >> 2);
#pragma unroll
        for (int nt = 0; nt < 2; nt++) {
            const float* wrow = w2g + (n + nt * 8) * 64;
#pragma unroll
            for (int ks = 0; ks < 4; ks++) {
                int k0 = ks * 16 + 2 * (lane & 3);
                float2 f01 = *reinterpret_cast<const float2*>(wrow + k0);
                float2 f23 = *reinterpret_cast<const float2*>(wrow + k0 + 8);
                split2(f01.x, f01.y, bhi[nt][ks][0], blo[nt][ks][0]);
                split2(f23.x, f23.y, bhi[nt][ks][1], blo[nt][ks][1]);
            }
        }
    }
    __syncthreads();

    const int i0 = blockIdx.x * 4;
    float4 si[4];
#pragma unroll
    for (int rr = 0; rr < 4; rr++) si[rr] = s4[i0 + rr];

    // ---- neighbor scan (one pass, 4 rows) ----
    for (int j = tid; j < NPTS; j += 256) {
        float4 sj = s4[j];
#pragma unroll
        for (int rr = 0; rr < 4; rr++) {
            float dx = si[rr].x - sj.x, dy = si[rr].y - sj.y;
            if (dx * dx + dy * dy < 0.25f) {
                int pq = atomicAdd(&cnt[rr], 1);
                nbr[rr][pq] = j;
            }
        }
    }
    __syncthreads();
    if (tid < 4) cntp[tid] = cnt[tid];
    __syncthreads();

    // conv1 per-thread constants: channel pair {2*chp2, 2*chp2+1}
    const int chp2 = tid & 31;
    const int sb   = tid >> 5;           // slot base: slots {sb + 8j}
    const int ca = 2 * chp2, cb = ca + 1;
    const float wa0 = w1s[ca*5+0], wa1 = w1s[ca*5+1], wa2 = w1s[ca*5+2],
                wa3 = w1s[ca*5+3], wa4 = w1s[ca*5+4], bba = b1s[ca];
    const float wb0 = w1s[cb*5+0], wb1 = w1s[cb*5+1], wb2 = w1s[cb*5+2],
                wb3 = w1s[cb*5+3], wb4 = w1s[cb*5+4], bbb = b1s[cb];

    // ldmatrix per-lane address pieces (row stride 144B = conflict-free)
    const uint32_t lm_row = (uint32_t)(lane & 15) * 144 + (uint32_t)(lane >> 4) * 16;

    // ================= pool: per row, mma.sync conv2 =================
    for (int rr = 0; rr < 4; rr++) {
        const float4 sir = si[rr];
        const int    i   = i0 + rr;
        const int    cp  = cntp[rr];
        const int*   nb  = nbr[rr];
        const int nchunks = (cp + 63) >> 6;

        float pc[2][2];
        pc[0][0] = -1e30f; pc[0][1] = -1e30f; pc[1][0] = -1e30f; pc[1][1] = -1e30f;

        for (int chunk = 0; chunk < nchunks; chunk++) {
            // ---- conv1: fill h1 hi/lo for 64 slots (8 slots x 2 ch / thread) ----
#pragma unroll
            for (int jj = 0; jj < 8; jj++) {
                int sl  = sb + 8 * jj;
                int gsl = chunk * 64 + sl;
                int j   = (gsl < cp) ? nb[gsl] : i;   // self-pad (idempotent)
                float4 sj = s4[j];
                float dx = sir.x - sj.x, dy = sir.y - sj.y;
                float dz = sir.z - sj.z, dw = sir.w - sj.w;
                float ind = (j == i) ? 1.0f : 0.0f;
                float h0 = bba, h1 = bbb;
                h0 = fmaf(dx, wa0, h0);  h1 = fmaf(dx, wb0, h1);
                h0 = fmaf(dy, wa1, h0);  h1 = fmaf(dy, wb1, h1);
                h0 = fmaf(dz, wa2, h0);  h1 = fmaf(dz, wb2, h1);
                h0 = fmaf(dw, wa3, h0);  h1 = fmaf(dw, wb3, h1);
                h0 = fmaf(ind, wa4, h0); h1 = fmaf(ind, wb4, h1);
                h0 = fmaxf(h0, 0.0f);    h1 = fmaxf(h1, 0.0f);
                uint32_t hp, lp;
                split2(h0, h1, hp, lp);
                uint32_t off = (uint32_t)(sl * 144 + chp2 * 4);
                *reinterpret_cast<uint32_t*>(h1hi + off) = hp;
                *reinterpret_cast<uint32_t*>(h1lo + off) = lp;
            }
            __syncthreads();

            // ---- conv2 via mma: 4 mtiles x 4 ksteps x 2 ntiles x 3 terms ----
#pragma unroll
            for (int mt = 0; mt < 4; mt++) {
                float acc[2][4];
#pragma unroll
                for (int nt = 0; nt < 2; nt++)
#pragma unroll
                    for (int q = 0; q < 4; q++) acc[nt][q] = 0.0f;

#pragma unroll
                for (int ks = 0; ks < 4; ks++) {
                    uint32_t base = (uint32_t)(mt * 16 * 144 + ks * 32) + lm_row;
                    uint32_t ah0, ah1, ah2, ah3, al0, al1, al2, al3;
                    ldmat4(ah0, ah1, ah2, ah3, smb + H1HI_OFF + base);
                    ldmat4(al0, al1, al2, al3, smb + H1LO_OFF + base);
#pragma unroll
                    for (int nt = 0; nt < 2; nt++) {
                        mma_bf16(acc[nt][0], acc[nt][1], acc[nt][2], acc[nt][3],
                                 ah0, ah1, ah2, ah3, bhi[nt][ks][0], bhi[nt][ks][1]);
                        mma_bf16(acc[nt][0], acc[nt][1], acc[nt][2], acc[nt][3],
                                 ah0, ah1, ah2, ah3, blo[nt][ks][0], blo[nt][ks][1]);
                        mma_bf16(acc[nt][0], acc[nt][1], acc[nt][2], acc[nt][3],
                                 al0, al1, al2, al3, bhi[nt][ks][0], bhi[nt][ks][1]);
                    }
                }
                // running max over slots (rows g and g+8 of this mtile)
#pragma unroll
                for (int nt = 0; nt < 2; nt++) {
                    pc[nt][0] = fmaxf(pc[nt][0], fmaxf(acc[nt][0], acc[nt][2]));
                    pc[nt][1] = fmaxf(pc[nt][1], fmaxf(acc[nt][1], acc[nt][3]));
                }
            }
            __syncthreads();   // h1 reads done before next chunk's conv1
        }

        // reduce across lanes sharing the same column (xor 4, 8, 16)
#pragma unroll
        for (int nt = 0; nt < 2; nt++)
#pragma unroll
            for (int j = 0; j < 2; j++) {
                float v = pc[nt][j];
                v = fmaxf(v, __shfl_xor_sync(0xffffffffu, v, 4));
                v = fmaxf(v, __shfl_xor_sync(0xffffffffu, v, 8));
                v = fmaxf(v, __shfl_xor_sync(0xffffffffu, v, 16));
                pc[nt][j] = v;
            }
        if (lane < 4) {
#pragma unroll
            for (int nt = 0; nt < 2; nt++)
#pragma unroll
                for (int j = 0; j < 2; j++) {
                    int ch = wrp * 16 + nt * 8 + 2 * lane + j;
                    feat[rr][ch] = fmaxf(pc[nt][j] + b2s[ch], 0.0f);
                }
        }
        __syncthreads();
    }

    // ======================= PHASE T: trunk =======================
    unsigned long long* wP = reinterpret_cast<unsigned long long*>(smem_raw);
    float* w4  = reinterpret_cast<float*>(smem_raw + 34320);
    float* bb1 = reinterpret_cast<float*>(smem_raw + 35344);
    float* bb2 = reinterpret_cast<float*>(smem_raw + 35600);
    float* bb3 = reinterpret_cast<float*>(smem_raw + 36112);
    float* b4s = reinterpret_cast<float*>(smem_raw + 36368);
    float (*act)[132] = feat;

    const int w = wrp;
    const bool active = (w < 4);
    const int r = i0 + (active ? w : 0);

    float4 sv = make_float4(0.f, 0.f, 0.f, 0.f);
    float2 gv = make_float2(0.f, 0.f);
    if (active) {
        sv = reinterpret_cast<const float4*>(s)[r];
        gv = reinterpret_cast<const float2*>(g)[r];
        if (lane == 0) {
            act[w][128] = sv.x - gv.x;
            act[w][129] = sv.y - gv.y;
            act[w][130] = sv.z;
            act[w][131] = sv.w;
        }
    }

    const float4* f1w4 = reinterpret_cast<const float4*>(fc1w);
    float4 v1[8];
#pragma unroll
    for (int rr = 0; rr < 8; rr++) v1[rr] = f1w4[tid + 256 * rr];
    float4 v1x;
    if (tid < 64) v1x = f1w4[2048 + tid];

    if (tid < 64)  bb1[tid] = fc1b[tid];
    if (tid < 128) bb2[tid] = fc2b[tid];
    if (tid >= 128 && tid < 192) bb3[tid - 128] = fc3b[tid - 128];
    if (tid < 4)   b4s[tid] = fc4b[tid];
    if (tid < 64) {
        float4 v = reinterpret_cast<const float4*>(fc4w)[tid];
        int o = tid >> 4;
        int k = (tid << 2) & 63;
        w4[(k + 0) * 4 + o] = v.x; w4[(k + 1) * 4 + o] = v.y;
        w4[(k + 2) * 4 + o] = v.z; w4[(k + 3) * 4 + o] = v.w;
    }

#pragma unroll
    for (int rr = 0; rr < 8; rr++) {
        int e = (tid + 256 * rr) << 2;
        int o = e / 132;
        int k = e - o * 132;
        int k2 = k >> 1;
        wP[(k2 + 0) * 65 + o] = pack2(v1[rr].x, v1[rr].y);
        wP[(k2 + 1) * 65 + o] = pack2(v1[rr].z, v1[rr].w);
    }
    if (tid < 64) {
        int e = (2048 + tid) << 2;
        int o = e / 132;
        int k = e - o * 132;
        int k2 = k >> 1;
        wP[(k2 + 0) * 65 + o] = pack2(v1x.x, v1x.y);
        wP[(k2 + 1) * 65 + o] = pack2(v1x.z, v1x.w);
    }
    __syncthreads();

    const float4* f2w4 = reinterpret_cast<const float4*>(fc2w);
    float4 v2[8];
#pragma unroll
    for (int rr = 0; rr < 8; rr++) v2[rr] = f2w4[tid + 256 * rr];

    // L1: 132 -> 64
    {
        float a0 = 0.f, a1 = 0.f;
        if (active) {
            const unsigned long long* actp =
                reinterpret_cast<const unsigned long long*>(act[w]);
            unsigned long long a0p = 0ull, a1p = 0ull;
#pragma unroll 6
            for (int k2 = 0; k2 < 66; k2++) {
                unsigned long long ap = actp[k2];
                fma2(a0p, ap, wP[k2 * 65 + lane]);
                fma2(a1p, ap, wP[k2 * 65 + lane + 32]);
            }
            float2 f0 = unpack2(a0p), f1 = unpack2(a1p);
            a0 = fmaxf(f0.x + f0.y + bb1[lane], 0.0f);
            a1 = fmaxf(f1.x + f1.y + bb1[lane + 32], 0.0f);
        }
        __syncthreads();
        if (active) { act[w][lane] = a0; act[w][lane + 32] = a1; }
    }

#pragma unroll
    for (int rr = 0; rr < 8; rr++) {
        int e = (tid + 256 * rr) << 2;
        int o = e >> 6;
        int k = e & 63;
        int k2 = k >> 1;
        wP[(k2 + 0) * 129 + o] = pack2(v2[rr].x, v2[rr].y);
        wP[(k2 + 1) * 129 + o] = pack2(v2[rr].z, v2[rr].w);
    }
    __syncthreads();

    const float4* f3w4 = reinterpret_cast<const float4*>(fc3w);
    float4 v3[8];
#pragma unroll
    for (int rr = 0; rr < 8; rr++) v3[rr] = f3w4[tid + 256 * rr];

    // L2: 64 -> 128
    {
        float o0 = 0.f, o1 = 0.f, o2 = 0.f, o3 = 0.f;
        if (active) {
            const unsigned long long* actp =
                reinterpret_cast<const unsigned long long*>(act[w]);
            unsigned long long ac[4] = {0ull, 0ull, 0ull, 0ull};
#pragma unroll 4
            for (int k2 = 0; k2 < 32; k2++) {
                unsigned long long ap = actp[k2];
                fma2(ac[0], ap, wP[k2 * 129 + lane]);
                fma2(ac[1], ap, wP[k2 * 129 + lane + 32]);
                fma2(ac[2], ap, wP[k2 * 129 + lane + 64]);
                fma2(ac[3], ap, wP[k2 * 129 + lane + 96]);
            }
            { float2 f = unpack2(ac[0]); o0 = fmaxf(f.x + f.y + bb2[lane],      0.0f); }
            { float2 f = unpack2(ac[1]); o1 = fmaxf(f.x + f.y + bb2[lane + 32], 0.0f); }
            { float2 f = unpack2(ac[2]); o2 = fmaxf(f.x + f.y + bb2[lane + 64], 0.0f); }
            { float2 f = unpack2(ac[3]); o3 = fmaxf(f.x + f.y + bb2[lane + 96], 0.0f); }
        }
        __syncthreads();
        if (active) {
            act[w][lane] = o0; act[w][lane + 32] = o1;
            act[w][lane + 64] = o2; act[w][lane + 96] = o3;
        }
    }

#pragma unroll
    for (int rr = 0; rr < 8; rr++) {
        int e = (tid + 256 * rr) << 2;
        int o = e >> 7;
        int k = e & 127;
        int k2 = k >> 1;
        wP[(k2 + 0) * 65 + o] = pack2(v3[rr].x, v3[rr].y);
        wP[(k2 + 1) * 65 + o] = pack2(v3[rr].z, v3[rr].w);
    }
    __syncthreads();

    if (active) {
        // L3: 128 -> 64
        const unsigned long long* actp =
            reinterpret_cast<const unsigned long long*>(act[w]);
        unsigned long long a0p = 0ull, a1p = 0ull;
#pragma unroll 8
        for (int k2 = 0; k2 < 64; k2++) {
            unsigned long long ap = actp[k2];
            fma2(a0p, ap, wP[k2 * 65 + lane]);
            fma2(a1p, ap, wP[k2 * 65 + lane + 32]);
        }
        float2 f0 = unpack2(a0p), f1 = unpack2(a1p);
        float a0 = fmaxf(f0.x + f0.y + bb3[lane], 0.0f);
        float a1 = fmaxf(f1.x + f1.y + bb3[lane + 32], 0.0f);
        __syncwarp();
        act[w][lane] = a0; act[w][lane + 32] = a1;
        __syncwarp();

        // L4: 64 -> 4, sigmoid, gains
        int ol = lane & 3;
        float acc = b4s[ol];
#pragma unroll 4
        for (int k = 0; k < 64; k++)
            acc = fmaf(act[w][k], w4[k * 4 + ol], acc);
        float kv = 2.0f / (1.0f + expf(-acc)) - 1.0f;

        float k1 = __shfl_sync(0xffffffffu, kv, 0);
        float k2 = __shfl_sync(0xffffffffu, kv, 1);
        float k3 = __shfl_sync(0xffffffffu, kv, 2);
        float k4 = __shfl_sync(0xffffffffu, kv, 3);

        if (lane == 0) {
            float sg0 = sv.x - gv.x;
            float sg1 = sv.y - gv.y;
            out[r * 2 + 0] = -(k1 * sg0 + k2 * sv.z);
            out[r * 2 + 1] = -(k3 * sg1 + k4 * sv.w);
        }
    }
}

// ============================================================================
extern "C" void kernel_launch(void* const* d_in, const int* in_sizes, int n_in,
                              void* d_out, int out_size)
{
    const float* s    = (const float*)d_in[0];
    const float* g    = (const float*)d_in[1];
    const float* c1w  = (const float*)d_in[2];
    const float* c1b  = (const float*)d_in[3];
    const float* c2w  = (const float*)d_in[4];
    const float* c2b  = (const float*)d_in[5];
    const float* f1w  = (const float*)d_in[6];
    const float* f1b  = (const float*)d_in[7];
    const float* f2w  = (const float*)d_in[8];
    const float* f2b  = (const float*)d_in[9];
    const float* f3w  = (const float*)d_in[10];
    const float* f3b  = (const float*)d_in[11];
    const float* f4w  = (const float*)d_in[12];
    const float* f4b  = (const float*)d_in[13];
    float* out = (float*)d_out;

    fused_kernel<<<NPTS / 4, 256>>>(s, g, c1w, c1b, c2w, c2b,
                                    f1w, f1b, f2w, f2b, f3w, f3b,
                                    f4w, f4b, out);
}